// round 2
// baseline (speedup 1.0000x reference)
#include <cuda_runtime.h>

typedef unsigned long long u64;
#define FULLM 0xffffffffu
#define NMAXP 1000000
#define VMAXP 200000

// ---- packed f32x2 helpers (sm_100+ PTX; ptxas will not auto-fuse these) ----
__device__ __forceinline__ u64 pack2(float a, float b) {
  u64 r;
  asm("mov.b64 %0, {%1, %2};" : "=l"(r) : "r"(__float_as_uint(a)), "r"(__float_as_uint(b)));
  return r;
}
__device__ __forceinline__ void unpack2(u64 v, float& a, float& b) {
  unsigned x, y;
  asm("mov.b64 {%0, %1}, %2;" : "=r"(x), "=r"(y) : "l"(v));
  a = __uint_as_float(x); b = __uint_as_float(y);
}
__device__ __forceinline__ u64 fma2(u64 a, u64 b, u64 c) {
  u64 r; asm("fma.rn.f32x2 %0, %1, %2, %3;" : "=l"(r) : "l"(a), "l"(b), "l"(c)); return r;
}
__device__ __forceinline__ u64 mul2(u64 a, u64 b) {
  u64 r; asm("mul.rn.f32x2 %0, %1, %2;" : "=l"(r) : "l"(a), "l"(b)); return r;
}
__device__ __forceinline__ u64 relu2(u64 v) {
  float a, b; unpack2(v, a, b);
  return pack2(fmaxf(a, 0.0f), fmaxf(b, 0.0f));
}
__device__ __forceinline__ u64 lds2(const float2* p) {
  float2 v = *p; return pack2(v.x, v.y);
}
__device__ __forceinline__ void ld2q(const float2* p, u64& w0, u64& w1) {
  float4 v = *reinterpret_cast<const float4*>(p);
  w0 = pack2(v.x, v.y); w1 = pack2(v.z, v.w);
}

struct WP {
  const float *pe_w1,*pe_g1,*pe_b1,*pe_w2,*pe_g2,*pe_b2,*pe_w3,*pe_g3,*pe_b3;
  const float *ve_w1,*ve_g1,*ve_b1,*ve_w2,*ve_g2,*ve_b2;
  const float *fu_w,*fu_g,*fu_b;
  const float *cl_w1,*cl_g1,*cl_b1;
  const float *ax_w1,*ax_g1,*ax_b1;
  const int   *pv_raw;
};

// ---- folded weights (bn scale folded into columns) ----
static __device__ float g_w_pe1[4*32],  g_b_pe1[32];
static __device__ float g_w_pe2[32*64], g_b_pe2[64];
static __device__ float g_w_pe3[64*32], g_b_pe3[32];
static __device__ float g_w_ve1[32*32], g_b_ve1[32];
static __device__ float g_w_ve2[32*32], g_b_ve2[32];
static __device__ float g_w_fu [64*64], g_b_fu [64];
static __device__ float g_w_cl1[64*32], g_b_cl1[32];
static __device__ float g_w_ax1[32*32], g_b_ax1[32];

// ---- scratch ----
static __device__ int      g_pv_is64;
static __device__ int      g_pv[NMAXP];
static __device__ float    g_pf[32*NMAXP];       // SoA [c][N]
static __device__ unsigned g_vmax[VMAXP*32];     // row-major [V][32]
static __device__ float    g_vf[VMAXP*32];       // row-major [V][32]
static __device__ float    g_fused[64*NMAXP];    // SoA [c][N]
static __device__ float    g_bsum[4*64];
static __device__ unsigned g_bcnt[4];
static __device__ float    g_gp1[4*64];          // 1 + gate

__device__ __forceinline__ void fold_w(float* dw, float* db,
    const float* W, const float* g, const float* b, int fi, int fo) {
  const float inv = 1.0f / sqrtf(1.0f + 1e-5f);
  for (int t = threadIdx.x; t < fi*fo; t += blockDim.x) dw[t] = W[t] * (g[t % fo] * inv);
  for (int t = threadIdx.x; t < fo;    t += blockDim.x) db[t] = b[t];
}

__global__ void k_prep(WP p) {
  fold_w(g_w_pe1, g_b_pe1, p.pe_w1, p.pe_g1, p.pe_b1, 4, 32);
  fold_w(g_w_pe2, g_b_pe2, p.pe_w2, p.pe_g2, p.pe_b2, 32, 64);
  fold_w(g_w_pe3, g_b_pe3, p.pe_w3, p.pe_g3, p.pe_b3, 64, 32);
  fold_w(g_w_ve1, g_b_ve1, p.ve_w1, p.ve_g1, p.ve_b1, 32, 32);
  fold_w(g_w_ve2, g_b_ve2, p.ve_w2, p.ve_g2, p.ve_b2, 32, 32);
  fold_w(g_w_fu,  g_b_fu,  p.fu_w,  p.fu_g,  p.fu_b,  64, 64);
  fold_w(g_w_cl1, g_b_cl1, p.cl_w1, p.cl_g1, p.cl_b1, 64, 32);
  fold_w(g_w_ax1, g_b_ax1, p.ax_w1, p.ax_g1, p.ax_b1, 32, 32);
  if (threadIdx.x == 0) {
    int z = 1;
    for (int k = 1; k < 128; k += 2) if (p.pv_raw[k] != 0) { z = 0; break; }
    g_pv_is64 = z;
  }
}

__global__ void k_init(const void* pv_raw, int N, int V) {
  int i = blockIdx.x * blockDim.x + threadIdx.x;
  if (i < N) {
    g_pv[i] = g_pv_is64 ? (int)((const long long*)pv_raw)[i]
                        : ((const int*)pv_raw)[i];
  }
  if (i < 32*V) g_vmax[i] = 0u;
  if (i < 256)  g_bsum[i] = 0.0f;
  if (i < 4)    g_bcnt[i] = 0u;
}

// ---- per-point MLP 4->32->64->32 (2 points/thread, f32x2), scatter segment_max ----
__global__ void __launch_bounds__(128) k_points(const float* __restrict__ points, int N) {
  __shared__ __align__(16) float2 sw1[4*32];
  __shared__ __align__(16) float2 sw2[32*64];
  __shared__ __align__(16) float2 sw3[64*32];
  __shared__ float2 sb1[32], sb2[64], sb3[32];
  for (int t = threadIdx.x; t < 4*32;  t += 128) { float v = g_w_pe1[t]; sw1[t] = make_float2(v, v); }
  for (int t = threadIdx.x; t < 32*64; t += 128) { float v = g_w_pe2[t]; sw2[t] = make_float2(v, v); }
  for (int t = threadIdx.x; t < 64*32; t += 128) { float v = g_w_pe3[t]; sw3[t] = make_float2(v, v); }
  if (threadIdx.x < 32) { float v = g_b_pe1[threadIdx.x]; sb1[threadIdx.x] = make_float2(v, v);
                          v = g_b_pe3[threadIdx.x]; sb3[threadIdx.x] = make_float2(v, v); }
  if (threadIdx.x < 64) { float v = g_b_pe2[threadIdx.x]; sb2[threadIdx.x] = make_float2(v, v); }
  __syncthreads();
  int t = blockIdx.x * 128 + threadIdx.x;
  int i0 = 2*t, i1 = 2*t + 1;
  if (i0 >= N) return;
  bool a1 = i1 < N;
  const float* p0 = points + (size_t)i0 * 5;
  const float* p1 = points + (size_t)(a1 ? i1 : i0) * 5;
  u64 x[4];
  #pragma unroll
  for (int j = 0; j < 4; j++) x[j] = pack2(p0[1+j], p1[1+j]);

  u64 h1[32];
  #pragma unroll
  for (int o = 0; o < 32; o += 2) {
    u64 a0 = lds2(&sb1[o]), a1v = lds2(&sb1[o+1]);
    #pragma unroll
    for (int j = 0; j < 4; j++) {
      u64 w0, w1; ld2q(&sw1[j*32 + o], w0, w1);
      a0 = fma2(x[j], w0, a0); a1v = fma2(x[j], w1, a1v);
    }
    h1[o] = relu2(a0); h1[o+1] = relu2(a1v);
  }

  u64 h3[32];
  #pragma unroll
  for (int o = 0; o < 32; o++) h3[o] = lds2(&sb3[o]);

  #pragma unroll
  for (int c2 = 0; c2 < 8; c2++) {
    u64 tc[8];
    #pragma unroll
    for (int oo = 0; oo < 8; oo++) tc[oo] = lds2(&sb2[c2*8 + oo]);
    #pragma unroll
    for (int k = 0; k < 32; k++) {
      u64 hk = h1[k];
      #pragma unroll
      for (int oo = 0; oo < 8; oo += 2) {
        u64 w0, w1; ld2q(&sw2[k*64 + c2*8 + oo], w0, w1);
        tc[oo] = fma2(hk, w0, tc[oo]); tc[oo+1] = fma2(hk, w1, tc[oo+1]);
      }
    }
    #pragma unroll
    for (int oo = 0; oo < 8; oo++) {
      u64 hv = relu2(tc[oo]);
      int krow = (c2*8 + oo) * 32;
      #pragma unroll
      for (int o3 = 0; o3 < 32; o3 += 2) {
        u64 w0, w1; ld2q(&sw3[krow + o3], w0, w1);
        h3[o3] = fma2(hv, w0, h3[o3]); h3[o3+1] = fma2(hv, w1, h3[o3+1]);
      }
    }
  }

  int pv0 = g_pv[i0];
  int pv1 = a1 ? g_pv[i1] : pv0;
  unsigned* r0 = g_vmax + (size_t)pv0 * 32;
  unsigned* r1 = g_vmax + (size_t)pv1 * 32;
  #pragma unroll
  for (int o = 0; o < 32; o++) {
    u64 v = relu2(h3[o]);
    float lo, hi; unpack2(v, lo, hi);
    if (a1) *(float2*)(g_pf + (size_t)o*N + i0) = make_float2(lo, hi);
    else    g_pf[(size_t)o*N + i0] = lo;
    atomicMax(r0 + o, __float_as_uint(lo));
    if (a1) atomicMax(r1 + o, __float_as_uint(hi));
  }
}

// ---- per-voxel MLP + aux head (scalar, minor cost) ----
__global__ void __launch_bounds__(256) k_vox(float* __restrict__ aux_out,
                                             const float* __restrict__ ax_w2, int V) {
  __shared__ float s1[32*32], sb1v[32], s2[32*32], sb2v[32], sa[32*32], sba[32], sa2[32*20];
  __shared__ float so[256*21];
  for (int t = threadIdx.x; t < 32*32; t += blockDim.x) s1[t] = g_w_ve1[t];
  for (int t = threadIdx.x; t < 32;    t += blockDim.x) sb1v[t] = g_b_ve1[t];
  for (int t = threadIdx.x; t < 32*32; t += blockDim.x) s2[t] = g_w_ve2[t];
  for (int t = threadIdx.x; t < 32;    t += blockDim.x) sb2v[t] = g_b_ve2[t];
  for (int t = threadIdx.x; t < 32*32; t += blockDim.x) sa[t] = g_w_ax1[t];
  for (int t = threadIdx.x; t < 32;    t += blockDim.x) sba[t] = g_b_ax1[t];
  for (int t = threadIdx.x; t < 32*20; t += blockDim.x) sa2[t] = ax_w2[t];
  __syncthreads();
  int j = blockIdx.x * blockDim.x + threadIdx.x;
  bool act = j < V;
  if (act) {
    float vox[32];
    const uint4* vr = reinterpret_cast<const uint4*>(g_vmax + (size_t)j * 32);
    #pragma unroll
    for (int q = 0; q < 8; q++) {
      uint4 t = vr[q];
      vox[4*q+0] = __uint_as_float(t.x); vox[4*q+1] = __uint_as_float(t.y);
      vox[4*q+2] = __uint_as_float(t.z); vox[4*q+3] = __uint_as_float(t.w);
    }
    float v1[32];
    #pragma unroll
    for (int o = 0; o < 32; o++) {
      float a = sb1v[o];
      #pragma unroll
      for (int k = 0; k < 32; k++) a += vox[k] * s1[k*32+o];
      v1[o] = fmaxf(a, 0.0f);
    }
    float vfv[32];
    #pragma unroll
    for (int o = 0; o < 32; o++) {
      float a = sb2v[o];
      #pragma unroll
      for (int k = 0; k < 32; k++) a += v1[k] * s2[k*32+o];
      vfv[o] = fmaxf(a, 0.0f);
    }
    float4* vfr = reinterpret_cast<float4*>(g_vf + (size_t)j * 32);
    #pragma unroll
    for (int q = 0; q < 8; q++) vfr[q] = make_float4(vfv[4*q], vfv[4*q+1], vfv[4*q+2], vfv[4*q+3]);
    float ah[32];
    #pragma unroll
    for (int o = 0; o < 32; o++) {
      float a = sba[o];
      #pragma unroll
      for (int k = 0; k < 32; k++) a += v1[k] * sa[k*32+o];
      ah[o] = fmaxf(a, 0.0f);
    }
    #pragma unroll
    for (int o = 0; o < 20; o++) {
      float a = 0.0f;
      #pragma unroll
      for (int k = 0; k < 32; k++) a += ah[k] * sa2[k*20+o];
      so[threadIdx.x*21 + o] = a;
    }
  }
  __syncthreads();
  int base = blockIdx.x * blockDim.x;
  int rows = V - base; if (rows > 256) rows = 256;
  if (rows > 0)
    for (int t = threadIdx.x; t < rows*20; t += blockDim.x)
      aux_out[(size_t)base*20 + t] = so[(t/20)*21 + (t%20)];
}

// ---- gather vf, concat pf, fuse 64->64 (2 pts/thread, f32x2), batch reduction ----
__global__ void __launch_bounds__(128) k_fuse(const float* __restrict__ points, int N) {
  __shared__ __align__(16) float2 sw[64*64];
  __shared__ float2 sb[64];
  __shared__ float swsum[4][64];
  __shared__ int   swb[4];
  for (int t = threadIdx.x; t < 64*64; t += 128) { float v = g_w_fu[t]; sw[t] = make_float2(v, v); }
  if (threadIdx.x < 64) { float v = g_b_fu[threadIdx.x]; sb[threadIdx.x] = make_float2(v, v); }
  __syncthreads();
  int t = blockIdx.x * 128 + threadIdx.x;
  int lane = threadIdx.x & 31, wid = threadIdx.x >> 5;
  int i0 = 2*t, i1 = 2*t + 1;
  bool act = i0 < N;
  bool a1  = i1 < N;
  u64 acc[64];
  int b0 = -1, b1 = -1;
  if (act) {
    #pragma unroll
    for (int o = 0; o < 64; o++) acc[o] = lds2(&sb[o]);
    int pv0 = g_pv[i0], pv1 = a1 ? g_pv[i1] : pv0;
    const float4* vr0 = (const float4*)(g_vf + (size_t)pv0 * 32);
    const float4* vr1 = (const float4*)(g_vf + (size_t)pv1 * 32);
    #pragma unroll
    for (int q = 0; q < 8; q++) {
      float4 A = vr0[q], Bv = vr1[q];
      u64 in4[4] = { pack2(A.x, Bv.x), pack2(A.y, Bv.y), pack2(A.z, Bv.z), pack2(A.w, Bv.w) };
      #pragma unroll
      for (int j = 0; j < 4; j++) {
        int k = q*4 + j; u64 ink = in4[j];
        #pragma unroll
        for (int o = 0; o < 64; o += 2) {
          u64 w0, w1; ld2q(&sw[k*64 + o], w0, w1);
          acc[o] = fma2(ink, w0, acc[o]); acc[o+1] = fma2(ink, w1, acc[o+1]);
        }
      }
    }
    #pragma unroll
    for (int c = 0; c < 32; c++) {
      int k = 32 + c;
      u64 ink;
      if (a1) { float2 pf2 = *(const float2*)(g_pf + (size_t)c*N + i0); ink = pack2(pf2.x, pf2.y); }
      else    ink = pack2(g_pf[(size_t)c*N + i0], 0.0f);
      #pragma unroll
      for (int o = 0; o < 64; o += 2) {
        u64 w0, w1; ld2q(&sw[k*64 + o], w0, w1);
        acc[o] = fma2(ink, w0, acc[o]); acc[o+1] = fma2(ink, w1, acc[o+1]);
      }
    }
    b0 = (int)points[(size_t)i0*5];
    b1 = a1 ? (int)points[(size_t)i1*5] : b0;
    #pragma unroll
    for (int o = 0; o < 64; o++) {
      u64 v = relu2(acc[o]);
      float lo, hi; unpack2(v, lo, hi);
      if (!a1) { hi = 0.0f; v = pack2(lo, 0.0f); }
      acc[o] = v;
      if (a1) *(float2*)(g_fused + (size_t)o*N + i0) = make_float2(lo, hi);
      else    g_fused[(size_t)o*N + i0] = lo;
    }
  }
  bool fast = __all_sync(FULLM, act && a1 && (b1 == b0)) &&
              (__match_any_sync(FULLM, b0) == FULLM);
  if (fast) {
    if (lane == 0) swb[wid] = b0;
    #pragma unroll
    for (int c = 0; c < 64; c++) {
      float lo, hi; unpack2(acc[c], lo, hi);
      float v = lo + hi;
      v += __shfl_xor_sync(FULLM, v, 16);
      v += __shfl_xor_sync(FULLM, v, 8);
      v += __shfl_xor_sync(FULLM, v, 4);
      v += __shfl_xor_sync(FULLM, v, 2);
      v += __shfl_xor_sync(FULLM, v, 1);
      if (lane == 0) swsum[wid][c] = v;
    }
  } else {
    if (lane == 0) swb[wid] = -1;
    if (act) {
      for (int c = 0; c < 64; c++) {
        float lo, hi; unpack2(acc[c], lo, hi);
        atomicAdd(&g_bsum[b0*64 + c], lo);
        if (a1) atomicAdd(&g_bsum[b1*64 + c], hi);
      }
      atomicAdd(&g_bcnt[b0], 1u);
      if (a1) atomicAdd(&g_bcnt[b1], 1u);
    }
  }
  __syncthreads();
  if (threadIdx.x < 64) {
    int c = threadIdx.x;
    int curb = -1; float cv = 0.0f;
    for (int w = 0; w < 4; w++) {
      int wb = swb[w];
      if (wb < 0) continue;
      if (wb != curb) { if (curb >= 0) atomicAdd(&g_bsum[curb*64 + c], cv); curb = wb; cv = 0.0f; }
      cv += swsum[w][c];
    }
    if (curb >= 0) atomicAdd(&g_bsum[curb*64 + c], cv);
  }
  if (threadIdx.x == 0) {
    int curb = -1; unsigned cc = 0;
    for (int w = 0; w < 4; w++) {
      int wb = swb[w];
      if (wb < 0) continue;
      if (wb != curb) { if (curb >= 0) atomicAdd(&g_bcnt[curb], cc); curb = wb; cc = 0; }
      cc += 64;
    }
    if (curb >= 0) atomicAdd(&g_bcnt[curb], cc);
  }
}

// ---- SE gate (tiny) ----
__global__ void k_se(const float* __restrict__ se_w1, const float* __restrict__ se_b1,
                     const float* __restrict__ se_w2, const float* __restrict__ se_b2) {
  __shared__ float mean[4*64], t1[16];
  int tid = threadIdx.x;
  int b = tid >> 6, c = tid & 63;
  mean[tid] = g_bsum[tid] / fmaxf((float)g_bcnt[b], 1.0f);
  __syncthreads();
  if (tid < 16) {
    int bb = tid >> 2, jj = tid & 3;
    float a = se_b1[jj];
    for (int k = 0; k < 64; k++) a += mean[bb*64 + k] * se_w1[k*4 + jj];
    t1[tid] = fmaxf(a, 0.0f);
  }
  __syncthreads();
  {
    float a = se_b2[c];
    #pragma unroll
    for (int jj = 0; jj < 4; jj++) a += t1[b*4 + jj] * se_w2[jj*64 + c];
    g_gp1[tid] = 1.0f + 1.0f / (1.0f + expf(-a));
  }
}

// ---- classifier head: gate-scale, 64->32->20 (2 pts/thread, f32x2) ----
__global__ void __launch_bounds__(128) k_out(const float* __restrict__ points,
                                             const float* __restrict__ cl_w2,
                                             float* __restrict__ out, int N) {
  __shared__ __align__(16) float2 sw1[64*32];
  __shared__ __align__(16) float2 sw2[32*20];
  __shared__ float2 sb1[32];
  __shared__ float sg[256];
  __shared__ float so[256*21];
  for (int t = threadIdx.x; t < 64*32; t += 128) { float v = g_w_cl1[t]; sw1[t] = make_float2(v, v); }
  for (int t = threadIdx.x; t < 32*20; t += 128) { float v = cl_w2[t]; sw2[t] = make_float2(v, v); }
  if (threadIdx.x < 32) { float v = g_b_cl1[threadIdx.x]; sb1[threadIdx.x] = make_float2(v, v); }
  for (int t = threadIdx.x; t < 256; t += 128) sg[t] = g_gp1[t];
  __syncthreads();
  int t = blockIdx.x * 128 + threadIdx.x;
  int i0 = 2*t, i1 = 2*t + 1;
  bool act = i0 < N, a1 = i1 < N;
  if (act) {
    int b0 = (int)points[(size_t)i0*5];
    int b1 = a1 ? (int)points[(size_t)i1*5] : b0;
    u64 h[32];
    #pragma unroll
    for (int o = 0; o < 32; o++) h[o] = lds2(&sb1[o]);
    #pragma unroll
    for (int k = 0; k < 64; k++) {
      u64 f;
      if (a1) { float2 fv = *(const float2*)(g_fused + (size_t)k*N + i0); f = pack2(fv.x, fv.y); }
      else    f = pack2(g_fused[(size_t)k*N + i0], 0.0f);
      u64 gk = pack2(sg[b0*64 + k], sg[b1*64 + k]);
      f = mul2(f, gk);
      #pragma unroll
      for (int o = 0; o < 32; o += 2) {
        u64 w0, w1; ld2q(&sw1[k*32 + o], w0, w1);
        h[o] = fma2(f, w0, h[o]); h[o+1] = fma2(f, w1, h[o+1]);
      }
    }
    #pragma unroll
    for (int o = 0; o < 32; o++) h[o] = relu2(h[o]);
    int r0 = 2*threadIdx.x, r1 = r0 + 1;
    #pragma unroll
    for (int o = 0; o < 20; o += 2) {
      u64 a0 = 0, a1v = 0;
      #pragma unroll
      for (int k = 0; k < 32; k++) {
        u64 w0, w1; ld2q(&sw2[k*20 + o], w0, w1);
        a0 = fma2(h[k], w0, a0); a1v = fma2(h[k], w1, a1v);
      }
      float l0, h0v, l1, h1v; unpack2(a0, l0, h0v); unpack2(a1v, l1, h1v);
      so[r0*21 + o] = l0; so[r0*21 + o + 1] = l1;
      so[r1*21 + o] = h0v; so[r1*21 + o + 1] = h1v;
    }
  }
  __syncthreads();
  int base = blockIdx.x * 256;
  int rows = N - base; if (rows > 256) rows = 256;
  if (rows > 0)
    for (int q = threadIdx.x; q < rows*20; q += 128)
      out[(size_t)base*20 + q] = so[(q/20)*21 + (q%20)];
}

extern "C" void kernel_launch(void* const* d_in, const int* in_sizes, int n_in,
                              void* d_out, int out_size) {
  const float* points = (const float*)d_in[0];
  int N = in_sizes[0] / 5;
  int V = (out_size - N * 20) / 20;
  float* out = (float*)d_out;
  float* aux_out = out + (size_t)N * 20;

  WP wp;
  wp.pe_w1 = (const float*)d_in[2];  wp.pe_g1 = (const float*)d_in[3];  wp.pe_b1 = (const float*)d_in[4];
  wp.pe_w2 = (const float*)d_in[5];  wp.pe_g2 = (const float*)d_in[6];  wp.pe_b2 = (const float*)d_in[7];
  wp.pe_w3 = (const float*)d_in[8];  wp.pe_g3 = (const float*)d_in[9];  wp.pe_b3 = (const float*)d_in[10];
  wp.ve_w1 = (const float*)d_in[11]; wp.ve_g1 = (const float*)d_in[12]; wp.ve_b1 = (const float*)d_in[13];
  wp.ve_w2 = (const float*)d_in[14]; wp.ve_g2 = (const float*)d_in[15]; wp.ve_b2 = (const float*)d_in[16];
  wp.fu_w  = (const float*)d_in[17]; wp.fu_g  = (const float*)d_in[18]; wp.fu_b  = (const float*)d_in[19];
  wp.cl_w1 = (const float*)d_in[24]; wp.cl_g1 = (const float*)d_in[25]; wp.cl_b1 = (const float*)d_in[26];
  wp.ax_w1 = (const float*)d_in[28]; wp.ax_g1 = (const float*)d_in[29]; wp.ax_b1 = (const float*)d_in[30];
  wp.pv_raw = (const int*)d_in[1];

  k_prep<<<1, 256>>>(wp);

  int tot = 32 * V; if (N > tot) tot = N;
  k_init<<<(tot + 255) / 256, 256>>>(d_in[1], N, V);

  int NP = (N + 1) / 2;
  k_points<<<(NP + 127) / 128, 128>>>(points, N);
  k_vox<<<(V + 255) / 256, 256>>>(aux_out, (const float*)d_in[31], V);
  k_fuse<<<(NP + 127) / 128, 128>>>(points, N);
  k_se<<<1, 256>>>((const float*)d_in[20], (const float*)d_in[21],
                   (const float*)d_in[22], (const float*)d_in[23]);
  k_out<<<(NP + 127) / 128, 128>>>(points, (const float*)d_in[27], out, N);
}

// round 3
// speedup vs baseline: 1.9047x; 1.9047x over previous
#include <cuda_runtime.h>

typedef unsigned long long u64;
#define FULLM 0xffffffffu
#define NMAXP 1000000
#define VMAXP 200000

// ---- packed f32x2 helpers ----
__device__ __forceinline__ u64 pack2(float a, float b) {
  u64 r;
  asm("mov.b64 %0, {%1, %2};" : "=l"(r) : "r"(__float_as_uint(a)), "r"(__float_as_uint(b)));
  return r;
}
__device__ __forceinline__ void unpack2(u64 v, float& a, float& b) {
  unsigned x, y;
  asm("mov.b64 {%0, %1}, %2;" : "=r"(x), "=r"(y) : "l"(v));
  a = __uint_as_float(x); b = __uint_as_float(y);
}
__device__ __forceinline__ u64 bcast2(float v) { return pack2(v, v); }
__device__ __forceinline__ u64 fma2(u64 a, u64 b, u64 c) {
  u64 r; asm("fma.rn.f32x2 %0, %1, %2, %3;" : "=l"(r) : "l"(a), "l"(b), "l"(c)); return r;
}
__device__ __forceinline__ u64 add2(u64 a, u64 b) {
  u64 r; asm("add.rn.f32x2 %0, %1, %2;" : "=l"(r) : "l"(a), "l"(b)); return r;
}
__device__ __forceinline__ u64 relu2(u64 v) {
  float a, b; unpack2(v, a, b);
  return pack2(fmaxf(a, 0.0f), fmaxf(b, 0.0f));
}
// 8B load from float array (index must be even)
__device__ __forceinline__ u64 lds2(const float* p) {
  float2 v = *reinterpret_cast<const float2*>(p); return pack2(v.x, v.y);
}
// 16B load from float array (index must be mult of 4)
__device__ __forceinline__ void ld2q(const float* p, u64& w0, u64& w1) {
  float4 v = *reinterpret_cast<const float4*>(p);
  w0 = pack2(v.x, v.y); w1 = pack2(v.z, v.w);
}

struct WP {
  const float *pe_w1,*pe_g1,*pe_b1,*pe_w2,*pe_g2,*pe_b2,*pe_w3,*pe_g3,*pe_b3;
  const float *ve_w1,*ve_g1,*ve_b1,*ve_w2,*ve_g2,*ve_b2;
  const float *fu_w,*fu_g,*fu_b;
  const float *cl_w1,*cl_g1,*cl_b1;
  const float *ax_w1,*ax_g1,*ax_b1;
  const int   *pv_raw;
};

// ---- folded weights ----
static __device__ float g_w_pe1[4*32],  g_b_pe1[32];
static __device__ float g_w_pe2[32*64], g_b_pe2[64];
static __device__ float g_w_pe3[64*32], g_b_pe3[32];
static __device__ float g_w_ve1[32*32], g_b_ve1[32];
static __device__ float g_w_ve2[32*32], g_b_ve2[32];
static __device__ float g_w_fu [64*64], g_b_fu [64];
static __device__ float g_w_cl1[64*32], g_b_cl1[32];
static __device__ float g_w_ax1[32*32], g_b_ax1[32];

// ---- scratch ----
static __device__ int      g_pv_is64;
static __device__ int      g_pv[NMAXP];
static __device__ float    g_pf[32*NMAXP];       // SoA [c][N]
static __device__ unsigned g_vmax[VMAXP*32];     // [V][32]
static __device__ float    g_vf[VMAXP*32];       // [V][32]
static __device__ float    g_fused[64*NMAXP];    // SoA [c][N]
static __device__ float    g_bsum[4*64];
static __device__ unsigned g_bcnt[4];
static __device__ float    g_gp1[4*64];

__device__ __forceinline__ void fold_w(float* dw, float* db,
    const float* W, const float* g, const float* b, int fi, int fo) {
  const float inv = 1.0f / sqrtf(1.0f + 1e-5f);
  for (int t = threadIdx.x; t < fi*fo; t += blockDim.x) dw[t] = W[t] * (g[t % fo] * inv);
  for (int t = threadIdx.x; t < fo;    t += blockDim.x) db[t] = b[t];
}

__global__ void k_prep(WP p) {
  fold_w(g_w_pe1, g_b_pe1, p.pe_w1, p.pe_g1, p.pe_b1, 4, 32);
  fold_w(g_w_pe2, g_b_pe2, p.pe_w2, p.pe_g2, p.pe_b2, 32, 64);
  fold_w(g_w_pe3, g_b_pe3, p.pe_w3, p.pe_g3, p.pe_b3, 64, 32);
  fold_w(g_w_ve1, g_b_ve1, p.ve_w1, p.ve_g1, p.ve_b1, 32, 32);
  fold_w(g_w_ve2, g_b_ve2, p.ve_w2, p.ve_g2, p.ve_b2, 32, 32);
  fold_w(g_w_fu,  g_b_fu,  p.fu_w,  p.fu_g,  p.fu_b,  64, 64);
  fold_w(g_w_cl1, g_b_cl1, p.cl_w1, p.cl_g1, p.cl_b1, 64, 32);
  fold_w(g_w_ax1, g_b_ax1, p.ax_w1, p.ax_g1, p.ax_b1, 32, 32);
  if (threadIdx.x == 0) {
    int z = 1;
    for (int k = 1; k < 128; k += 2) if (p.pv_raw[k] != 0) { z = 0; break; }
    g_pv_is64 = z;
  }
}

__global__ void k_init(const void* pv_raw, int N, int V) {
  int i = blockIdx.x * blockDim.x + threadIdx.x;
  if (i < N) {
    g_pv[i] = g_pv_is64 ? (int)((const long long*)pv_raw)[i]
                        : ((const int*)pv_raw)[i];
  }
  if (i < 32*V) g_vmax[i] = 0u;
  if (i < 256)  g_bsum[i] = 0.0f;
  if (i < 4)    g_bcnt[i] = 0u;
}

// ---- per-point MLP 4->32->64->32, packed output pairs ----
__global__ void __launch_bounds__(128) k_points(const float* __restrict__ points, int N) {
  __shared__ __align__(16) float sw1[4*32], sw2[32*64], sw3[64*32];
  __shared__ __align__(16) float sb1[32], sb2[64], sb3[32];
  for (int t = threadIdx.x; t < 4*32;  t += 128) sw1[t] = g_w_pe1[t];
  for (int t = threadIdx.x; t < 32*64; t += 128) sw2[t] = g_w_pe2[t];
  for (int t = threadIdx.x; t < 64*32; t += 128) sw3[t] = g_w_pe3[t];
  if (threadIdx.x < 32) { sb1[threadIdx.x] = g_b_pe1[threadIdx.x]; sb3[threadIdx.x] = g_b_pe3[threadIdx.x]; }
  if (threadIdx.x < 64) sb2[threadIdx.x] = g_b_pe2[threadIdx.x];
  __syncthreads();
  int i = blockIdx.x * 128 + threadIdx.x;
  if (i >= N) return;
  const float* pr = points + (size_t)i * 5;
  float x[4] = { pr[1], pr[2], pr[3], pr[4] };

  // L1: 4 -> 32
  u64 a1[16];
  #pragma unroll
  for (int o2 = 0; o2 < 16; o2++) a1[o2] = lds2(sb1 + 2*o2);
  #pragma unroll
  for (int j = 0; j < 4; j++) {
    u64 xj = bcast2(x[j]);
    #pragma unroll
    for (int o4 = 0; o4 < 32; o4 += 4) {
      u64 w0, w1; ld2q(sw1 + j*32 + o4, w0, w1);
      a1[o4/2] = fma2(xj, w0, a1[o4/2]); a1[o4/2+1] = fma2(xj, w1, a1[o4/2+1]);
    }
  }
  #pragma unroll
  for (int o2 = 0; o2 < 16; o2++) a1[o2] = relu2(a1[o2]);

  // L2: 32 -> 64
  u64 a2[32];
  #pragma unroll
  for (int o2 = 0; o2 < 32; o2++) a2[o2] = lds2(sb2 + 2*o2);
  #pragma unroll
  for (int k2 = 0; k2 < 16; k2++) {
    float h0, h1v; unpack2(a1[k2], h0, h1v);
    u64 hb = bcast2(h0);
    const float* row = sw2 + (2*k2)*64;
    #pragma unroll
    for (int o4 = 0; o4 < 64; o4 += 4) {
      u64 w0, w1; ld2q(row + o4, w0, w1);
      a2[o4/2] = fma2(hb, w0, a2[o4/2]); a2[o4/2+1] = fma2(hb, w1, a2[o4/2+1]);
    }
    hb = bcast2(h1v);
    row = sw2 + (2*k2+1)*64;
    #pragma unroll
    for (int o4 = 0; o4 < 64; o4 += 4) {
      u64 w0, w1; ld2q(row + o4, w0, w1);
      a2[o4/2] = fma2(hb, w0, a2[o4/2]); a2[o4/2+1] = fma2(hb, w1, a2[o4/2+1]);
    }
  }
  #pragma unroll
  for (int o2 = 0; o2 < 32; o2++) a2[o2] = relu2(a2[o2]);

  // L3: 64 -> 32
  u64 a3[16];
  #pragma unroll
  for (int o2 = 0; o2 < 16; o2++) a3[o2] = lds2(sb3 + 2*o2);
  #pragma unroll
  for (int k2 = 0; k2 < 32; k2++) {
    float h0, h1v; unpack2(a2[k2], h0, h1v);
    u64 hb = bcast2(h0);
    const float* row = sw3 + (2*k2)*32;
    #pragma unroll
    for (int o4 = 0; o4 < 32; o4 += 4) {
      u64 w0, w1; ld2q(row + o4, w0, w1);
      a3[o4/2] = fma2(hb, w0, a3[o4/2]); a3[o4/2+1] = fma2(hb, w1, a3[o4/2+1]);
    }
    hb = bcast2(h1v);
    row = sw3 + (2*k2+1)*32;
    #pragma unroll
    for (int o4 = 0; o4 < 32; o4 += 4) {
      u64 w0, w1; ld2q(row + o4, w0, w1);
      a3[o4/2] = fma2(hb, w0, a3[o4/2]); a3[o4/2+1] = fma2(hb, w1, a3[o4/2+1]);
    }
  }

  int pv = g_pv[i];
  unsigned* vrow = g_vmax + (size_t)pv * 32;
  #pragma unroll
  for (int o2 = 0; o2 < 16; o2++) {
    u64 v = relu2(a3[o2]);
    float lo, hi; unpack2(v, lo, hi);
    g_pf[(size_t)(2*o2)*N + i] = lo;
    g_pf[(size_t)(2*o2+1)*N + i] = hi;
    atomicMax(vrow + 2*o2,     __float_as_uint(lo));
    atomicMax(vrow + 2*o2 + 1, __float_as_uint(hi));
  }
}

// ---- per-voxel MLP + aux head, packed pairs ----
__global__ void __launch_bounds__(128) k_vox(float* __restrict__ aux_out,
                                             const float* __restrict__ ax_w2, int V) {
  __shared__ __align__(16) float s1[32*32], s2[32*32], sa[32*32], sa2[32*20];
  __shared__ __align__(16) float sb1v[32], sb2v[32], sba[32];
  __shared__ float so[128*21];
  for (int t = threadIdx.x; t < 32*32; t += 128) { s1[t] = g_w_ve1[t]; s2[t] = g_w_ve2[t]; sa[t] = g_w_ax1[t]; }
  for (int t = threadIdx.x; t < 32*20; t += 128) sa2[t] = ax_w2[t];
  if (threadIdx.x < 32) { sb1v[threadIdx.x] = g_b_ve1[threadIdx.x]; sb2v[threadIdx.x] = g_b_ve2[threadIdx.x]; sba[threadIdx.x] = g_b_ax1[threadIdx.x]; }
  __syncthreads();
  int j = blockIdx.x * 128 + threadIdx.x;
  bool act = j < V;
  if (act) {
    float vox[32];
    const uint4* vr = reinterpret_cast<const uint4*>(g_vmax + (size_t)j * 32);
    #pragma unroll
    for (int q = 0; q < 8; q++) {
      uint4 t = vr[q];
      vox[4*q+0] = __uint_as_float(t.x); vox[4*q+1] = __uint_as_float(t.y);
      vox[4*q+2] = __uint_as_float(t.z); vox[4*q+3] = __uint_as_float(t.w);
    }
    // ve1: 32->32
    u64 v1[16];
    #pragma unroll
    for (int o2 = 0; o2 < 16; o2++) v1[o2] = lds2(sb1v + 2*o2);
    #pragma unroll
    for (int k = 0; k < 32; k++) {
      u64 hb = bcast2(vox[k]);
      const float* row = s1 + k*32;
      #pragma unroll
      for (int o4 = 0; o4 < 32; o4 += 4) {
        u64 w0, w1; ld2q(row + o4, w0, w1);
        v1[o4/2] = fma2(hb, w0, v1[o4/2]); v1[o4/2+1] = fma2(hb, w1, v1[o4/2+1]);
      }
    }
    #pragma unroll
    for (int o2 = 0; o2 < 16; o2++) v1[o2] = relu2(v1[o2]);
    // ve2: 32->32, write g_vf
    {
      u64 vf[16];
      #pragma unroll
      for (int o2 = 0; o2 < 16; o2++) vf[o2] = lds2(sb2v + 2*o2);
      #pragma unroll
      for (int k2 = 0; k2 < 16; k2++) {
        float h0, h1v; unpack2(v1[k2], h0, h1v);
        u64 hb = bcast2(h0);
        const float* row = s2 + (2*k2)*32;
        #pragma unroll
        for (int o4 = 0; o4 < 32; o4 += 4) {
          u64 w0, w1; ld2q(row + o4, w0, w1);
          vf[o4/2] = fma2(hb, w0, vf[o4/2]); vf[o4/2+1] = fma2(hb, w1, vf[o4/2+1]);
        }
        hb = bcast2(h1v);
        row = s2 + (2*k2+1)*32;
        #pragma unroll
        for (int o4 = 0; o4 < 32; o4 += 4) {
          u64 w0, w1; ld2q(row + o4, w0, w1);
          vf[o4/2] = fma2(hb, w0, vf[o4/2]); vf[o4/2+1] = fma2(hb, w1, vf[o4/2+1]);
        }
      }
      float* vfr = g_vf + (size_t)j * 32;
      #pragma unroll
      for (int o2 = 0; o2 < 16; o2++) {
        u64 v = relu2(vf[o2]);
        float lo, hi; unpack2(v, lo, hi);
        *reinterpret_cast<float2*>(vfr + 2*o2) = make_float2(lo, hi);
      }
    }
    // aux: 32->32 relu, then 32->20
    {
      u64 ah[16];
      #pragma unroll
      for (int o2 = 0; o2 < 16; o2++) ah[o2] = lds2(sba + 2*o2);
      #pragma unroll
      for (int k2 = 0; k2 < 16; k2++) {
        float h0, h1v; unpack2(v1[k2], h0, h1v);
        u64 hb = bcast2(h0);
        const float* row = sa + (2*k2)*32;
        #pragma unroll
        for (int o4 = 0; o4 < 32; o4 += 4) {
          u64 w0, w1; ld2q(row + o4, w0, w1);
          ah[o4/2] = fma2(hb, w0, ah[o4/2]); ah[o4/2+1] = fma2(hb, w1, ah[o4/2+1]);
        }
        hb = bcast2(h1v);
        row = sa + (2*k2+1)*32;
        #pragma unroll
        for (int o4 = 0; o4 < 32; o4 += 4) {
          u64 w0, w1; ld2q(row + o4, w0, w1);
          ah[o4/2] = fma2(hb, w0, ah[o4/2]); ah[o4/2+1] = fma2(hb, w1, ah[o4/2+1]);
        }
      }
      u64 acc[10];
      #pragma unroll
      for (int o2 = 0; o2 < 10; o2++) acc[o2] = 0;
      #pragma unroll
      for (int k2 = 0; k2 < 16; k2++) {
        u64 hv = relu2(ah[k2]);
        float h0, h1v; unpack2(hv, h0, h1v);
        u64 hb = bcast2(h0);
        const float* row = sa2 + (2*k2)*20;
        #pragma unroll
        for (int o2 = 0; o2 < 10; o2++) acc[o2] = fma2(hb, lds2(row + 2*o2), acc[o2]);
        hb = bcast2(h1v);
        row = sa2 + (2*k2+1)*20;
        #pragma unroll
        for (int o2 = 0; o2 < 10; o2++) acc[o2] = fma2(hb, lds2(row + 2*o2), acc[o2]);
      }
      #pragma unroll
      for (int o2 = 0; o2 < 10; o2++) {
        float lo, hi; unpack2(acc[o2], lo, hi);
        so[threadIdx.x*21 + 2*o2] = lo; so[threadIdx.x*21 + 2*o2 + 1] = hi;
      }
    }
  }
  __syncthreads();
  int base = blockIdx.x * 128;
  int rows = V - base; if (rows > 128) rows = 128;
  if (rows > 0)
    for (int t = threadIdx.x; t < rows*20; t += 128)
      aux_out[(size_t)base*20 + t] = so[(t/20)*21 + (t%20)];
}

// ---- gather vf, concat pf, fuse 64->64 packed, batch reduction ----
__global__ void __launch_bounds__(128) k_fuse(const float* __restrict__ points, int N) {
  __shared__ __align__(16) float sw[64*64], sb[64];
  __shared__ float swsum[4][64];
  __shared__ int   swb[4];
  for (int t = threadIdx.x; t < 64*64; t += 128) sw[t] = g_w_fu[t];
  if (threadIdx.x < 64) sb[threadIdx.x] = g_b_fu[threadIdx.x];
  __syncthreads();
  int i = blockIdx.x * 128 + threadIdx.x;
  int lane = threadIdx.x & 31, wid = threadIdx.x >> 5;
  bool act = i < N;
  int b = -1;
  u64 acc[32];
  if (act) {
    #pragma unroll
    for (int o2 = 0; o2 < 32; o2++) acc[o2] = lds2(sb + 2*o2);
    int pv = g_pv[i];
    const float4* vr = reinterpret_cast<const float4*>(g_vf + (size_t)pv * 32);
    #pragma unroll
    for (int q = 0; q < 8; q++) {
      float4 A = vr[q];
      float in4[4] = { A.x, A.y, A.z, A.w };
      #pragma unroll
      for (int jj = 0; jj < 4; jj++) {
        u64 hb = bcast2(in4[jj]);
        const float* row = sw + (q*4 + jj)*64;
        #pragma unroll
        for (int o4 = 0; o4 < 64; o4 += 4) {
          u64 w0, w1; ld2q(row + o4, w0, w1);
          acc[o4/2] = fma2(hb, w0, acc[o4/2]); acc[o4/2+1] = fma2(hb, w1, acc[o4/2+1]);
        }
      }
    }
    #pragma unroll
    for (int c = 0; c < 32; c++) {
      u64 hb = bcast2(g_pf[(size_t)c*N + i]);
      const float* row = sw + (32 + c)*64;
      #pragma unroll
      for (int o4 = 0; o4 < 64; o4 += 4) {
        u64 w0, w1; ld2q(row + o4, w0, w1);
        acc[o4/2] = fma2(hb, w0, acc[o4/2]); acc[o4/2+1] = fma2(hb, w1, acc[o4/2+1]);
      }
    }
    b = (int)points[(size_t)i*5];
  }
  bool fast = (__match_any_sync(FULLM, b) == FULLM);
  if (lane == 0) swb[wid] = (fast && b >= 0) ? b : -1;
  #pragma unroll
  for (int o2 = 0; o2 < 32; o2++) {
    float lo = 0.0f, hi = 0.0f;
    if (act) {
      u64 v = relu2(acc[o2]);
      unpack2(v, lo, hi);
      g_fused[(size_t)(2*o2)*N + i] = lo;
      g_fused[(size_t)(2*o2+1)*N + i] = hi;
    }
    if (fast) {
      if (b >= 0) {
        u64 v = pack2(lo, hi);
        v = add2(v, __shfl_xor_sync(FULLM, v, 16));
        v = add2(v, __shfl_xor_sync(FULLM, v, 8));
        v = add2(v, __shfl_xor_sync(FULLM, v, 4));
        v = add2(v, __shfl_xor_sync(FULLM, v, 2));
        v = add2(v, __shfl_xor_sync(FULLM, v, 1));
        if (lane == 0) {
          float sl, sh; unpack2(v, sl, sh);
          swsum[wid][2*o2] = sl; swsum[wid][2*o2+1] = sh;
        }
      }
    } else if (act) {
      atomicAdd(&g_bsum[b*64 + 2*o2],     lo);
      atomicAdd(&g_bsum[b*64 + 2*o2 + 1], hi);
    }
  }
  if (!fast && act) atomicAdd(&g_bcnt[b], 1u);
  __syncthreads();
  if (threadIdx.x < 64) {
    int c = threadIdx.x;
    int curb = -1; float cv = 0.0f;
    for (int w = 0; w < 4; w++) {
      int wb = swb[w];
      if (wb < 0) continue;
      if (wb != curb) { if (curb >= 0) atomicAdd(&g_bsum[curb*64 + c], cv); curb = wb; cv = 0.0f; }
      cv += swsum[w][c];
    }
    if (curb >= 0) atomicAdd(&g_bsum[curb*64 + c], cv);
  }
  if (threadIdx.x == 0) {
    int curb = -1; unsigned cc = 0;
    for (int w = 0; w < 4; w++) {
      int wb = swb[w];
      if (wb < 0) continue;
      if (wb != curb) { if (curb >= 0) atomicAdd(&g_bcnt[curb], cc); curb = wb; cc = 0; }
      cc += 32;
    }
    if (curb >= 0) atomicAdd(&g_bcnt[curb], cc);
  }
}

// ---- SE gate ----
__global__ void k_se(const float* __restrict__ se_w1, const float* __restrict__ se_b1,
                     const float* __restrict__ se_w2, const float* __restrict__ se_b2) {
  __shared__ float mean[4*64], t1[16];
  int tid = threadIdx.x;
  int b = tid >> 6, c = tid & 63;
  mean[tid] = g_bsum[tid] / fmaxf((float)g_bcnt[b], 1.0f);
  __syncthreads();
  if (tid < 16) {
    int bb = tid >> 2, jj = tid & 3;
    float a = se_b1[jj];
    for (int k = 0; k < 64; k++) a += mean[bb*64 + k] * se_w1[k*4 + jj];
    t1[tid] = fmaxf(a, 0.0f);
  }
  __syncthreads();
  {
    float a = se_b2[c];
    #pragma unroll
    for (int jj = 0; jj < 4; jj++) a += t1[b*4 + jj] * se_w2[jj*64 + c];
    g_gp1[tid] = 1.0f + 1.0f / (1.0f + expf(-a));
  }
}

// ---- classifier head: gate-scale, 64->32->20, packed ----
__global__ void __launch_bounds__(128) k_out(const float* __restrict__ points,
                                             const float* __restrict__ cl_w2,
                                             float* __restrict__ out, int N) {
  __shared__ __align__(16) float sw1[64*32], sw2[32*20], sb1c[32];
  __shared__ float sg[256];
  __shared__ float so[128*21];
  for (int t = threadIdx.x; t < 64*32; t += 128) sw1[t] = g_w_cl1[t];
  for (int t = threadIdx.x; t < 32*20; t += 128) sw2[t] = cl_w2[t];
  if (threadIdx.x < 32) sb1c[threadIdx.x] = g_b_cl1[threadIdx.x];
  for (int t = threadIdx.x; t < 256; t += 128) sg[t] = g_gp1[t];
  __syncthreads();
  int i = blockIdx.x * 128 + threadIdx.x;
  bool act = i < N;
  if (act) {
    int b = (int)points[(size_t)i*5];
    const float* gb = sg + b*64;
    u64 h[16];
    #pragma unroll
    for (int o2 = 0; o2 < 16; o2++) h[o2] = lds2(sb1c + 2*o2);
    #pragma unroll
    for (int k = 0; k < 64; k++) {
      float f = g_fused[(size_t)k*N + i] * gb[k];
      u64 hb = bcast2(f);
      const float* row = sw1 + k*32;
      #pragma unroll
      for (int o4 = 0; o4 < 32; o4 += 4) {
        u64 w0, w1; ld2q(row + o4, w0, w1);
        h[o4/2] = fma2(hb, w0, h[o4/2]); h[o4/2+1] = fma2(hb, w1, h[o4/2+1]);
      }
    }
    u64 acc[10];
    #pragma unroll
    for (int o2 = 0; o2 < 10; o2++) acc[o2] = 0;
    #pragma unroll
    for (int k2 = 0; k2 < 16; k2++) {
      u64 hv = relu2(h[k2]);
      float h0, h1v; unpack2(hv, h0, h1v);
      u64 hb = bcast2(h0);
      const float* row = sw2 + (2*k2)*20;
      #pragma unroll
      for (int o2 = 0; o2 < 10; o2++) acc[o2] = fma2(hb, lds2(row + 2*o2), acc[o2]);
      hb = bcast2(h1v);
      row = sw2 + (2*k2+1)*20;
      #pragma unroll
      for (int o2 = 0; o2 < 10; o2++) acc[o2] = fma2(hb, lds2(row + 2*o2), acc[o2]);
    }
    #pragma unroll
    for (int o2 = 0; o2 < 10; o2++) {
      float lo, hi; unpack2(acc[o2], lo, hi);
      so[threadIdx.x*21 + 2*o2] = lo; so[threadIdx.x*21 + 2*o2 + 1] = hi;
    }
  }
  __syncthreads();
  int base = blockIdx.x * 128;
  int rows = N - base; if (rows > 128) rows = 128;
  if (rows > 0)
    for (int q = threadIdx.x; q < rows*20; q += 128)
      out[(size_t)base*20 + q] = so[(q/20)*21 + (q%20)];
}

extern "C" void kernel_launch(void* const* d_in, const int* in_sizes, int n_in,
                              void* d_out, int out_size) {
  const float* points = (const float*)d_in[0];
  int N = in_sizes[0] / 5;
  int V = (out_size - N * 20) / 20;
  float* out = (float*)d_out;
  float* aux_out = out + (size_t)N * 20;

  WP wp;
  wp.pe_w1 = (const float*)d_in[2];  wp.pe_g1 = (const float*)d_in[3];  wp.pe_b1 = (const float*)d_in[4];
  wp.pe_w2 = (const float*)d_in[5];  wp.pe_g2 = (const float*)d_in[6];  wp.pe_b2 = (const float*)d_in[7];
  wp.pe_w3 = (const float*)d_in[8];  wp.pe_g3 = (const float*)d_in[9];  wp.pe_b3 = (const float*)d_in[10];
  wp.ve_w1 = (const float*)d_in[11]; wp.ve_g1 = (const float*)d_in[12]; wp.ve_b1 = (const float*)d_in[13];
  wp.ve_w2 = (const float*)d_in[14]; wp.ve_g2 = (const float*)d_in[15]; wp.ve_b2 = (const float*)d_in[16];
  wp.fu_w  = (const float*)d_in[17]; wp.fu_g  = (const float*)d_in[18]; wp.fu_b  = (const float*)d_in[19];
  wp.cl_w1 = (const float*)d_in[24]; wp.cl_g1 = (const float*)d_in[25]; wp.cl_b1 = (const float*)d_in[26];
  wp.ax_w1 = (const float*)d_in[28]; wp.ax_g1 = (const float*)d_in[29]; wp.ax_b1 = (const float*)d_in[30];
  wp.pv_raw = (const int*)d_in[1];

  k_prep<<<1, 256>>>(wp);

  int tot = 32 * V; if (N > tot) tot = N;
  k_init<<<(tot + 255) / 256, 256>>>(d_in[1], N, V);

  k_points<<<(N + 127) / 128, 128>>>(points, N);
  k_vox<<<(V + 127) / 128, 128>>>(aux_out, (const float*)d_in[31], V);
  k_fuse<<<(N + 127) / 128, 128>>>(points, N);
  k_se<<<1, 256>>>((const float*)d_in[20], (const float*)d_in[21],
                   (const float*)d_in[22], (const float*)d_in[23]);
  k_out<<<(N + 127) / 128, 128>>>(points, (const float*)d_in[27], out, N);
}